// round 7
// baseline (speedup 1.0000x reference)
#include <cuda_runtime.h>
#include <cuda_bf16.h>
#include <stdint.h>

// ---------------------------------------------------------------------------
// Hodge1LapEdgeEncoder
//
// Output (float32): [0,P) idx rows | [P,2P) idx cols | [2P,2P+P*D) dense vals
//   dense[slot, :] = padding + sum_{e: slot(e)==slot} (edge_attr[e] + pestat[e,0]*fc_w)
//   slot(e) = u * n + (v % n),  u = ei[0,e] (dense row id), v = ei[1,e]
//
// Tier 1 (fast): bin edges by slot (CAP=8, exact overflow spill), then a
//   gather-style streaming pass writes every output float4 exactly once.
//   No shared memory, no atomics in the hot kernel.
// Tier 2: init + global red.v4 scatter (proven R4 path).
// Tier 3: fully generic scalar path.
// ---------------------------------------------------------------------------

#define TB 256
#define CAP 8                          // binned edges per slot
#define CNT_MAX (1 << 20)              // max slots (P) supported by scratch
#define OVF_MAX (1 << 17)              // max spilled edges

__device__ int g_cnt[CNT_MAX];         // zero .bss; dense kernel self-resets
__device__ int g_bin[CNT_MAX * CAP];
__device__ int g_ovf;                  // spill counter (ovf kernel resets)
__device__ int g_ovfe[OVF_MAX];        // spilled edge ids

// ===========================================================================
// Tier 1 kernel A: slot binning + idx pattern (fused, block-partitioned).
// ===========================================================================
__global__ void k_bin_idx(const int* __restrict__ ei, int E,
                          float* __restrict__ out, long long P,
                          int sn, int binBlocks)
{
    const int tid = threadIdx.x;
    if ((int)blockIdx.x < binBlocks) {
        int e = blockIdx.x * TB + tid;
        if (e >= E) return;
        int u  = __ldg(&ei[e]);
        int rv = __ldg(&ei[E + e]) & ((1 << sn) - 1);
        int slot = (u << sn) | rv;
        int pos = atomicAdd(&g_cnt[slot], 1);
        if (pos < CAP) {
            g_bin[slot * CAP + pos] = e;
        } else {
            int o = atomicAdd(&g_ovf, 1);
            if (o < OVF_MAX) g_ovfe[o] = e;
        }
        return;
    }
    // idx pattern, float4-vectorized (host guarantees n % 4 == 0)
    long long P4 = P >> 2;
    long long t = (long long)((int)blockIdx.x - binBlocks) * TB + tid;
    if (t >= P4) return;
    long long q = t << 2;
    int nm1  = (1 << sn) - 1;
    long long nnm1 = ((long long)1 << (2 * sn)) - 1;
    int b   = (int)(q >> (2 * sn));
    int rem = (int)(q & nnm1);
    int i   = rem >> sn;
    int j   = rem & nm1;
    float rv = (float)((b << sn) + i);
    float cv = (float)((b << sn) + j);
    ((float4*)out)[t]       = make_float4(rv, rv, rv, rv);
    ((float4*)(out + P))[t] = make_float4(cv, cv + 1.f, cv + 2.f, cv + 3.f);
}

// ===========================================================================
// Tier 1 kernel B: gather-style dense pass. One thread per output float4.
// Writes each output exactly once; resets cnt for the next replay.
// Requires D4 = 1<<s4 with s4 <= 5 (slot's threads live in one warp).
// ===========================================================================
__global__ void k_dense(float4* __restrict__ val4,        // dense as float4
                        const float*  __restrict__ pestat,// [E, K]
                        const float4* __restrict__ ea4,   // [E, D4]
                        const float4* __restrict__ w4,    // [D4]
                        const float4* __restrict__ pad4,  // [D4]
                        long long total4, int K, int s4)
{
    long long t = (long long)blockIdx.x * TB + threadIdx.x;
    if (t >= total4) return;
    int  c    = (int)t & ((1 << s4) - 1);
    long long slot = t >> s4;

    int m = g_cnt[slot];          // warp-uniform per slot-group, coalesced

    float4 acc = __ldg(&pad4[c]);
    if (m > 0) {
        float4 w = __ldg(&w4[c]);
        int mm = m < CAP ? m : CAP;
        const int* bl = &g_bin[slot * CAP];
        #pragma unroll 4
        for (int j = 0; j < mm; j++) {
            int e = __ldg(&bl[j]);
            float  p = __ldg(&pestat[(long long)e * K]);
            float4 a = __ldg(&ea4[((long long)e << s4) + c]);
            acc.x += a.x + p * w.x;
            acc.y += a.y + p * w.y;
            acc.z += a.z + p * w.z;
            acc.w += a.w + p * w.w;
        }
        if (c == 0) g_cnt[slot] = 0;    // reset for next replay
    }
    val4[t] = acc;
}

// ===========================================================================
// Tier 1 kernel C: apply spilled edges (expected empty), reset spill counter.
// Single block so the reset can follow a __syncthreads.
// ===========================================================================
__device__ __forceinline__ void red_add_v4(float* dst, float4 r)
{
#if __CUDA_ARCH__ >= 900
    asm volatile("red.global.add.v4.f32 [%0], {%1, %2, %3, %4};"
                 :: "l"(dst), "f"(r.x), "f"(r.y), "f"(r.z), "f"(r.w)
                 : "memory");
#else
    atomicAdd(dst + 0, r.x); atomicAdd(dst + 1, r.y);
    atomicAdd(dst + 2, r.z); atomicAdd(dst + 3, r.w);
#endif
}

__global__ void k_ovf(float* __restrict__ val,
                      const int* __restrict__ ei,
                      const float* __restrict__ pestat,
                      const float4* __restrict__ ea4,
                      const float4* __restrict__ w4,
                      int E, int K, int s4, int sn)
{
    int m = g_ovf;
    if (m > OVF_MAX) m = OVF_MAX;
    int D4 = 1 << s4;
    for (int i = threadIdx.x; i < m * D4; i += TB) {
        int li = i >> s4;
        int c  = i & (D4 - 1);
        int e  = g_ovfe[li];
        int u  = __ldg(&ei[e]);
        int rv = __ldg(&ei[E + e]) & ((1 << sn) - 1);
        long long slot = ((long long)u << sn) | rv;
        float  p = __ldg(&pestat[(long long)e * K]);
        float4 a = __ldg(&ea4[((long long)e << s4) + c]);
        float4 w = __ldg(&w4[c]);
        float4 r = make_float4(a.x + p * w.x, a.y + p * w.y,
                               a.z + p * w.z, a.w + p * w.w);
        red_add_v4(val + (slot << (s4 + 2)) + (c << 2), r);
    }
    __syncthreads();
    if (threadIdx.x == 0) g_ovf = 0;
}

// ===========================================================================
// Tier 2: R4 pow2 two-kernel path (init + global vector atomics).
// ===========================================================================
__global__ void k_init_p2(float* __restrict__ out, const float4* __restrict__ pad4,
                          int sn, long long P, int D4, int idxBlocks)
{
    if ((int)blockIdx.x < idxBlocks) {
        long long P4 = P >> 2;
        long long t = (long long)blockIdx.x * blockDim.x + threadIdx.x;
        if (t >= P4) return;
        long long q = t << 2;
        int nm1  = (1 << sn) - 1;
        long long nnm1 = ((long long)1 << (2 * sn)) - 1;
        int b   = (int)(q >> (2 * sn));
        int rem = (int)(q & nnm1);
        int i   = rem >> sn;
        int j   = rem & nm1;
        float rv = (float)((b << sn) + i);
        float cv = (float)((b << sn) + j);
        ((float4*)out)[t]       = make_float4(rv, rv, rv, rv);
        ((float4*)(out + P))[t] = make_float4(cv, cv + 1.f, cv + 2.f, cv + 3.f);
    } else {
        long long v = (long long)((int)blockIdx.x - idxBlocks) * blockDim.x
                      + threadIdx.x;
        long long V4 = P * (long long)D4;
        if (v >= V4) return;
        int c = (int)threadIdx.x & (D4 - 1);
        ((float4*)(out + 2 * P))[v] = __ldg(&pad4[c]);
    }
}

__global__ void k_scatter_p2(const int* __restrict__ ei, const float* __restrict__ pestat,
                             const float4* __restrict__ ea4, const float4* __restrict__ w4,
                             float* __restrict__ val, int E, int K, int s4, int sn)
{
    int tot = E << s4;
    int t = blockIdx.x * blockDim.x + threadIdx.x;
    if (t >= tot) return;
    int e = t >> s4;
    int c = t & ((1 << s4) - 1);
    int u = __ldg(&ei[e]);
    int rv = __ldg(&ei[E + e]) & ((1 << sn) - 1);

    float  p = __ldg(&pestat[(long long)e * K]);
    float4 a = __ldg(&ea4[((long long)e << s4) + c]);
    float4 w = __ldg(&w4[c]);
    float4 rr = make_float4(a.x + p * w.x, a.y + p * w.y,
                            a.z + p * w.z, a.w + p * w.w);
    long long slot = ((long long)u << sn) | rv;
    red_add_v4(val + (slot << (s4 + 2)) + (c << 2), rr);
}

// ===========================================================================
// Tier 3: fully generic fallbacks.
// ===========================================================================
__global__ void k_init_fused_s(float* __restrict__ out, const float* __restrict__ pad,
                               long long P, int n, int D)
{
    long long totalI = P;
    long long tot = P + P * (long long)D;
    float* val = out + 2 * P;
    long long stride = (long long)gridDim.x * blockDim.x;
    for (long long t = (long long)blockIdx.x * blockDim.x + threadIdx.x;
         t < tot; t += stride) {
        if (t < totalI) {
            long long nn = (long long)n * n;
            int b   = (int)(t / nn);
            int rem = (int)(t - (long long)b * nn);
            int i   = rem / n;
            int j   = rem - i * n;
            out[t]     = (float)(b * n + i);
            out[P + t] = (float)(b * n + j);
        } else {
            long long v = t - totalI;
            val[v] = __ldg(&pad[(int)(v % D)]);
        }
    }
}

__global__ void k_scatter_s(const int* __restrict__ ei, const float* __restrict__ pestat,
                            const float* __restrict__ ea, const float* __restrict__ w,
                            float* __restrict__ val, int E, int K, int D, int n)
{
    long long tot = (long long)E * D;
    long long stride = (long long)gridDim.x * blockDim.x;
    for (long long t = (long long)blockIdx.x * blockDim.x + threadIdx.x;
         t < tot; t += stride) {
        int e = (int)(t / D);
        int d = (int)(t - (long long)e * D);
        int u = __ldg(&ei[e]);
        int v = __ldg(&ei[E + e]);
        int g  = u / n;
        int ru = u - g * n;
        int rv = v % n;
        float p = __ldg(&pestat[(long long)e * K]);
        float x = ea[(long long)e * D + d] + p * __ldg(&w[d]);
        long long base = (((long long)g * n + ru) * n + rv) * (long long)D + d;
        atomicAdd(val + base, x);
    }
}

// ===========================================================================

static inline bool is_pow2(int x) { return x > 0 && (x & (x - 1)) == 0; }
static inline int  ilog2(int x)   { int s = 0; while ((1 << s) < x) s++; return s; }
static inline int grid_for(long long work, int tb)
{
    long long g = (work + tb - 1) / tb;
    if (g > 1048576) g = 1048576;
    if (g < 1) g = 1;
    return (int)g;
}

extern "C" void kernel_launch(void* const* d_in, const int* in_sizes, int n_in,
                              void* d_out, int out_size)
{
    // metadata order: edge_index, pestat, edge_attr, batch, fc_w, padding
    const int*   ei     = (const int*)  d_in[0];
    const float* pestat = (const float*)d_in[1];
    const float* ea     = (const float*)d_in[2];
    const float* fc_w   = (const float*)d_in[4];
    const float* pad    = (const float*)d_in[5];

    const int E = in_sizes[0] / 2;
    const int K = in_sizes[1] / E;
    const int D = in_sizes[2] / E;
    const int N = in_sizes[3];                            // dense rows = B*n
    const long long P = (long long)out_size / (D + 2);    // slots = B*n*n
    const int n = (int)(P / N);

    float* out = (float*)d_out;
    float* val = out + 2 * P;
    const int D4 = D / 4;

    const bool pow2ok = (D % 4 == 0) && (n % 4 == 0) &&
                        is_pow2(n) && is_pow2(D4) && D4 <= 256 &&
                        ((long long)E * D4 < (1LL << 31));

    const bool fastok = pow2ok && D4 <= 32 && P <= CNT_MAX && E <= OVF_MAX &&
                        (long long)P == (long long)N * n;

    if (fastok) {
        const int sn = ilog2(n);
        const int s4 = ilog2(D4);
        const int binBlocks = (E + TB - 1) / TB;
        const int idxBlocks = (int)(((P >> 2) + TB - 1) / TB);
        const long long total4 = P * (long long)D4;

        k_bin_idx<<<binBlocks + idxBlocks, TB>>>(ei, E, out, P, sn, binBlocks);
        k_dense<<<(int)((total4 + TB - 1) / TB), TB>>>((float4*)val, pestat,
                                                       (const float4*)ea,
                                                       (const float4*)fc_w,
                                                       (const float4*)pad,
                                                       total4, K, s4);
        k_ovf<<<1, TB>>>(val, ei, pestat, (const float4*)ea,
                         (const float4*)fc_w, E, K, s4, sn);
    } else if (pow2ok) {
        const int sn = ilog2(n);
        const int s4 = ilog2(D4);
        long long P4 = P >> 2;
        long long V4 = P * (long long)D4;
        int idxBlocks = (int)((P4 + TB - 1) / TB);
        int valBlocks = (int)((V4 + TB - 1) / TB);
        k_init_p2<<<idxBlocks + valBlocks, TB>>>(out, (const float4*)pad,
                                                 sn, P, D4, idxBlocks);
        int tot = E << s4;
        k_scatter_p2<<<(tot + TB - 1) / TB, TB>>>(ei, pestat,
                                                  (const float4*)ea,
                                                  (const float4*)fc_w,
                                                  val, E, K, s4, sn);
    } else {
        long long tot = P + P * (long long)D;
        k_init_fused_s<<<grid_for(tot, TB), TB>>>(out, pad, P, n, D);
        long long st = (long long)E * D;
        k_scatter_s<<<grid_for(st, TB), TB>>>(ei, pestat, ea, fc_w, val,
                                              E, K, D, n);
    }
}

// round 8
// speedup vs baseline: 1.0105x; 1.0105x over previous
#include <cuda_runtime.h>
#include <cuda_bf16.h>
#include <stdint.h>

// ---------------------------------------------------------------------------
// Hodge1LapEdgeEncoder
//
// Output (float32): [0,P) idx rows | [P,2P) idx cols | [2P,2P+P*D) dense vals
//   dense[slot,:] = padding + sum_{e: slot(e)==slot} (edge_attr[e] + pestat[e,0]*fc_w)
//   slot(e) = u*n + (v%n),  u = ei[0,e], v = ei[1,e]
//
// Tier 1: K_A  init (idx pattern + padding broadcast, R4-proven) with edge
//              binning blocks appended (independent -> overlapped).
//         K_B  apply: per dirty slot, overwrite whole 256B slot row with
//              padding + sum (exclusive owner -> plain stores, no atomics).
//         K_C  spill edges via red.v4 (expected empty) + counter resets.
// Tier 2: R4 init + global red.v4 scatter.  Tier 3: generic scalar.
// ---------------------------------------------------------------------------

#define TB 256
#define CAP 8                           // binned edges per slot
#define CNT_MAX (1 << 20)               // max slots (P)
#define DIRTY_MAX (1 << 17)             // max distinct dirty slots (>= E)
#define OVF_MAX (1 << 17)               // max spilled edges

__device__ int g_cnt[CNT_MAX];          // zero .bss; apply kernel self-resets
__device__ int g_bin[CNT_MAX * CAP];
__device__ int g_dirty[DIRTY_MAX];      // compact dirty-slot list
__device__ int g_ndirty;                // reset by K_C
__device__ int g_ovf;                   // reset by K_C
__device__ int g_ovfe[OVF_MAX];

// ===========================================================================
// Tier 1 K_A: idx pattern + padding init + edge binning (block-partitioned).
// ===========================================================================
__global__ void k_init_bin(float* __restrict__ out,
                           const float4* __restrict__ pad4,
                           const int* __restrict__ ei,
                           int E, int sn, long long P, int D4,
                           int idxBlocks, int valBlocks)
{
    const int tid = threadIdx.x;
    const int bid = blockIdx.x;

    if (bid < idxBlocks) {
        // ---- idx pattern (float4-vectorized; n % 4 == 0 by host guard) ----
        long long P4 = P >> 2;
        long long t = (long long)bid * TB + tid;
        if (t >= P4) return;
        long long q = t << 2;
        int nm1  = (1 << sn) - 1;
        long long nnm1 = ((long long)1 << (2 * sn)) - 1;
        int b   = (int)(q >> (2 * sn));
        int rem = (int)(q & nnm1);
        int i   = rem >> sn;
        int j   = rem & nm1;
        float rv = (float)((b << sn) + i);
        float cv = (float)((b << sn) + j);
        ((float4*)out)[t]       = make_float4(rv, rv, rv, rv);
        ((float4*)(out + P))[t] = make_float4(cv, cv + 1.f, cv + 2.f, cv + 3.f);
    } else if (bid < idxBlocks + valBlocks) {
        // ---- padding broadcast over dense region (R4-proven) ----
        long long v = (long long)(bid - idxBlocks) * TB + tid;
        long long V4 = P * (long long)D4;
        if (v >= V4) return;
        int c = tid & (D4 - 1);          // valid: 256 % D4 == 0 (D4 pow2 <= 256)
        ((float4*)(out + 2 * P))[v] = __ldg(&pad4[c]);
    } else {
        // ---- edge binning by slot ----
        int e = (bid - idxBlocks - valBlocks) * TB + tid;
        if (e >= E) return;
        int u  = __ldg(&ei[e]);
        int rv = __ldg(&ei[E + e]) & ((1 << sn) - 1);
        int slot = (u << sn) | rv;
        int pos = atomicAdd(&g_cnt[slot], 1);
        if (pos == 0) {
            int d = atomicAdd(&g_ndirty, 1);
            if (d < DIRTY_MAX) g_dirty[d] = slot;
        }
        if (pos < CAP) {
            g_bin[slot * CAP + pos] = e;
        } else {
            int o = atomicAdd(&g_ovf, 1);
            if (o < OVF_MAX) g_ovfe[o] = e;
        }
    }
}

// ===========================================================================
// Tier 1 K_B: apply. One thread per (dirty slot, float4 chunk). Exclusive
// owner of its slot -> plain store of padding + sum. Resets cnt per slot.
// ===========================================================================
__global__ void k_apply(float4* __restrict__ val4,
                        const float*  __restrict__ pestat,  // [E, K]
                        const float4* __restrict__ ea4,     // [E, D4]
                        const float4* __restrict__ w4,      // [D4]
                        const float4* __restrict__ pad4,    // [D4]
                        int K, int s4)
{
    int t  = blockIdx.x * TB + threadIdx.x;
    int li = t >> s4;
    int c  = t & ((1 << s4) - 1);
    int nd = g_ndirty;
    if (nd > DIRTY_MAX) nd = DIRTY_MAX;
    if (li >= nd) return;

    int slot = g_dirty[li];
    int m = g_cnt[slot];
    int mm = m < CAP ? m : CAP;

    float4 acc = __ldg(&pad4[c]);
    float4 w   = __ldg(&w4[c]);
    const int* bl = &g_bin[slot * CAP];
    for (int j = 0; j < mm; j++) {
        int e = __ldg(&bl[j]);
        float  p = __ldg(&pestat[(long long)e * K]);
        float4 a = __ldg(&ea4[((long long)e << s4) + c]);
        acc.x += a.x + p * w.x;
        acc.y += a.y + p * w.y;
        acc.z += a.z + p * w.z;
        acc.w += a.w + p * w.w;
    }
    val4[((long long)slot << s4) + c] = acc;
    if (c == 0) g_cnt[slot] = 0;         // ready for next replay
}

// ===========================================================================
// Tier 1 K_C: spilled edges (expected none) via red.v4; reset list counters.
// ===========================================================================
__device__ __forceinline__ void red_add_v4(float* dst, float4 r)
{
#if __CUDA_ARCH__ >= 900
    asm volatile("red.global.add.v4.f32 [%0], {%1, %2, %3, %4};"
                 :: "l"(dst), "f"(r.x), "f"(r.y), "f"(r.z), "f"(r.w)
                 : "memory");
#else
    atomicAdd(dst + 0, r.x); atomicAdd(dst + 1, r.y);
    atomicAdd(dst + 2, r.z); atomicAdd(dst + 3, r.w);
#endif
}

__global__ void k_ovf(float* __restrict__ val,
                      const int* __restrict__ ei,
                      const float* __restrict__ pestat,
                      const float4* __restrict__ ea4,
                      const float4* __restrict__ w4,
                      int E, int K, int s4, int sn)
{
    int m = g_ovf;
    if (m > OVF_MAX) m = OVF_MAX;
    int D4 = 1 << s4;
    for (int i = threadIdx.x; i < m * D4; i += TB) {
        int li = i >> s4;
        int c  = i & (D4 - 1);
        int e  = g_ovfe[li];
        int u  = __ldg(&ei[e]);
        int rv = __ldg(&ei[E + e]) & ((1 << sn) - 1);
        long long slot = ((long long)u << sn) | rv;
        float  p = __ldg(&pestat[(long long)e * K]);
        float4 a = __ldg(&ea4[((long long)e << s4) + c]);
        float4 w = __ldg(&w4[c]);
        float4 r = make_float4(a.x + p * w.x, a.y + p * w.y,
                               a.z + p * w.z, a.w + p * w.w);
        red_add_v4(val + (slot << (s4 + 2)) + (c << 2), r);
    }
    __syncthreads();
    if (threadIdx.x == 0) { g_ovf = 0; g_ndirty = 0; }
}

// ===========================================================================
// Tier 2: R4 pow2 two-kernel path (init + global vector atomics).
// ===========================================================================
__global__ void k_init_p2(float* __restrict__ out, const float4* __restrict__ pad4,
                          int sn, long long P, int D4, int idxBlocks)
{
    if ((int)blockIdx.x < idxBlocks) {
        long long P4 = P >> 2;
        long long t = (long long)blockIdx.x * blockDim.x + threadIdx.x;
        if (t >= P4) return;
        long long q = t << 2;
        int nm1  = (1 << sn) - 1;
        long long nnm1 = ((long long)1 << (2 * sn)) - 1;
        int b   = (int)(q >> (2 * sn));
        int rem = (int)(q & nnm1);
        int i   = rem >> sn;
        int j   = rem & nm1;
        float rv = (float)((b << sn) + i);
        float cv = (float)((b << sn) + j);
        ((float4*)out)[t]       = make_float4(rv, rv, rv, rv);
        ((float4*)(out + P))[t] = make_float4(cv, cv + 1.f, cv + 2.f, cv + 3.f);
    } else {
        long long v = (long long)((int)blockIdx.x - idxBlocks) * blockDim.x
                      + threadIdx.x;
        long long V4 = P * (long long)D4;
        if (v >= V4) return;
        int c = (int)threadIdx.x & (D4 - 1);
        ((float4*)(out + 2 * P))[v] = __ldg(&pad4[c]);
    }
}

__global__ void k_scatter_p2(const int* __restrict__ ei, const float* __restrict__ pestat,
                             const float4* __restrict__ ea4, const float4* __restrict__ w4,
                             float* __restrict__ val, int E, int K, int s4, int sn)
{
    int tot = E << s4;
    int t = blockIdx.x * blockDim.x + threadIdx.x;
    if (t >= tot) return;
    int e = t >> s4;
    int c = t & ((1 << s4) - 1);
    int u = __ldg(&ei[e]);
    int rv = __ldg(&ei[E + e]) & ((1 << sn) - 1);
    float  p = __ldg(&pestat[(long long)e * K]);
    float4 a = __ldg(&ea4[((long long)e << s4) + c]);
    float4 w = __ldg(&w4[c]);
    float4 rr = make_float4(a.x + p * w.x, a.y + p * w.y,
                            a.z + p * w.z, a.w + p * w.w);
    long long slot = ((long long)u << sn) | rv;
    red_add_v4(val + (slot << (s4 + 2)) + (c << 2), rr);
}

// ===========================================================================
// Tier 3: fully generic fallbacks.
// ===========================================================================
__global__ void k_init_fused_s(float* __restrict__ out, const float* __restrict__ pad,
                               long long P, int n, int D)
{
    long long totalI = P;
    long long tot = P + P * (long long)D;
    float* val = out + 2 * P;
    long long stride = (long long)gridDim.x * blockDim.x;
    for (long long t = (long long)blockIdx.x * blockDim.x + threadIdx.x;
         t < tot; t += stride) {
        if (t < totalI) {
            long long nn = (long long)n * n;
            int b   = (int)(t / nn);
            int rem = (int)(t - (long long)b * nn);
            int i   = rem / n;
            int j   = rem - i * n;
            out[t]     = (float)(b * n + i);
            out[P + t] = (float)(b * n + j);
        } else {
            long long v = t - totalI;
            val[v] = __ldg(&pad[(int)(v % D)]);
        }
    }
}

__global__ void k_scatter_s(const int* __restrict__ ei, const float* __restrict__ pestat,
                            const float* __restrict__ ea, const float* __restrict__ w,
                            float* __restrict__ val, int E, int K, int D, int n)
{
    long long tot = (long long)E * D;
    long long stride = (long long)gridDim.x * blockDim.x;
    for (long long t = (long long)blockIdx.x * blockDim.x + threadIdx.x;
         t < tot; t += stride) {
        int e = (int)(t / D);
        int d = (int)(t - (long long)e * D);
        int u = __ldg(&ei[e]);
        int v = __ldg(&ei[E + e]);
        int g  = u / n;
        int ru = u - g * n;
        int rv = v % n;
        float p = __ldg(&pestat[(long long)e * K]);
        float x = ea[(long long)e * D + d] + p * __ldg(&w[d]);
        long long base = (((long long)g * n + ru) * n + rv) * (long long)D + d;
        atomicAdd(val + base, x);
    }
}

// ===========================================================================

static inline bool is_pow2(int x) { return x > 0 && (x & (x - 1)) == 0; }
static inline int  ilog2(int x)   { int s = 0; while ((1 << s) < x) s++; return s; }
static inline int grid_for(long long work, int tb)
{
    long long g = (work + tb - 1) / tb;
    if (g > 1048576) g = 1048576;
    if (g < 1) g = 1;
    return (int)g;
}

extern "C" void kernel_launch(void* const* d_in, const int* in_sizes, int n_in,
                              void* d_out, int out_size)
{
    // metadata order: edge_index, pestat, edge_attr, batch, fc_w, padding
    const int*   ei     = (const int*)  d_in[0];
    const float* pestat = (const float*)d_in[1];
    const float* ea     = (const float*)d_in[2];
    const float* fc_w   = (const float*)d_in[4];
    const float* pad    = (const float*)d_in[5];

    const int E = in_sizes[0] / 2;
    const int K = in_sizes[1] / E;
    const int D = in_sizes[2] / E;
    const int N = in_sizes[3];                            // dense rows = B*n
    const long long P = (long long)out_size / (D + 2);    // slots = B*n*n
    const int n = (int)(P / N);

    float* out = (float*)d_out;
    float* val = out + 2 * P;
    const int D4 = D / 4;

    const bool pow2ok = (D % 4 == 0) && (n % 4 == 0) &&
                        is_pow2(n) && is_pow2(D4) && D4 <= 256 &&
                        ((long long)E * D4 < (1LL << 31));

    const bool fastok = pow2ok && D4 <= 32 && P <= CNT_MAX &&
                        E <= DIRTY_MAX && E <= OVF_MAX &&
                        (long long)P == (long long)N * n;

    if (fastok) {
        const int sn = ilog2(n);
        const int s4 = ilog2(D4);
        const int idxBlocks = (int)(((P >> 2) + TB - 1) / TB);
        const int valBlocks = (int)((P * (long long)D4 + TB - 1) / TB);
        const int binBlocks = (E + TB - 1) / TB;

        k_init_bin<<<idxBlocks + valBlocks + binBlocks, TB>>>(
            out, (const float4*)pad, ei, E, sn, P, D4, idxBlocks, valBlocks);

        long long maxDirty = (long long)E < P ? (long long)E : P;
        int applyBlocks = (int)((maxDirty * D4 + TB - 1) / TB);
        k_apply<<<applyBlocks, TB>>>((float4*)val, pestat,
                                     (const float4*)ea, (const float4*)fc_w,
                                     (const float4*)pad, K, s4);

        k_ovf<<<1, TB>>>(val, ei, pestat, (const float4*)ea,
                         (const float4*)fc_w, E, K, s4, sn);
    } else if (pow2ok) {
        const int sn = ilog2(n);
        const int s4 = ilog2(D4);
        long long P4 = P >> 2;
        long long V4 = P * (long long)D4;
        int idxBlocks = (int)((P4 + TB - 1) / TB);
        int valBlocks = (int)((V4 + TB - 1) / TB);
        k_init_p2<<<idxBlocks + valBlocks, TB>>>(out, (const float4*)pad,
                                                 sn, P, D4, idxBlocks);
        int tot = E << s4;
        k_scatter_p2<<<(tot + TB - 1) / TB, TB>>>(ei, pestat,
                                                  (const float4*)ea,
                                                  (const float4*)fc_w,
                                                  val, E, K, s4, sn);
    } else {
        long long tot = P + P * (long long)D;
        k_init_fused_s<<<grid_for(tot, TB), TB>>>(out, pad, P, n, D);
        long long st = (long long)E * D;
        k_scatter_s<<<grid_for(st, TB), TB>>>(ei, pestat, ea, fc_w, val,
                                              E, K, D, n);
    }
}

// round 10
// speedup vs baseline: 1.5039x; 1.4883x over previous
#include <cuda_runtime.h>
#include <cuda_bf16.h>
#include <stdint.h>

// ---------------------------------------------------------------------------
// Hodge1LapEdgeEncoder
//
// Output (float32): [0,P) idx rows | [P,2P) idx cols | [2P,2P+P*D) dense vals
//   dense[slot,:] = padding + sum_{e: slot(e)==slot} (edge_attr[e] + pestat[e,0]*fc_w)
//   slot(e) = u*n + (v%n),  u = ei[0,e], v = ei[1,e]
//
// Tier 1: K1  padding broadcast over dense region, 4x STG.128 per thread.
//         K2  idx-pattern blocks (leading bids, ride free) + red.v4 scatter.
// Tier 2: R4 path (single-store init + scatter).  Tier 3: generic scalar.
// ---------------------------------------------------------------------------

#define TB 256
#define IPT 4            // float4 stores per thread in K1

__device__ __forceinline__ void red_add_v4(float* dst, float4 r)
{
#if __CUDA_ARCH__ >= 900
    asm volatile("red.global.add.v4.f32 [%0], {%1, %2, %3, %4};"
                 :: "l"(dst), "f"(r.x), "f"(r.y), "f"(r.z), "f"(r.w)
                 : "memory");
#else
    atomicAdd(dst + 0, r.x); atomicAdd(dst + 1, r.y);
    atomicAdd(dst + 2, r.z); atomicAdd(dst + 3, r.w);
#endif
}

// ===========================================================================
// Tier 1 K1: padding broadcast init, IPT coalesced float4 stores per thread.
// Requires TB % D4 == 0 (D4 pow2 <= 256) so c depends only on tid.
// ===========================================================================
__global__ void k_init4(float4* __restrict__ val4,
                        const float4* __restrict__ pad4,
                        long long V4, int D4)
{
    long long base = (long long)blockIdx.x * (TB * IPT) + threadIdx.x;
    float4 pv = __ldg(&pad4[(int)threadIdx.x & (D4 - 1)]);
    #pragma unroll
    for (int k = 0; k < IPT; k++) {
        long long v = base + (long long)k * TB;
        if (v < V4) val4[v] = pv;
    }
}

// ===========================================================================
// Tier 1 K2: idx pattern (leading blocks) + edge scatter (red.v4).
// ===========================================================================
__global__ void k_idx_scatter(float* __restrict__ out, long long P,
                              const int* __restrict__ ei,
                              const float* __restrict__ pestat,
                              const float4* __restrict__ ea4,
                              const float4* __restrict__ w4,
                              float* __restrict__ val,
                              int E, int K, int s4, int sn,
                              int idxBlocks)
{
    const int tid = threadIdx.x;
    const int bid = blockIdx.x;

    if (bid < idxBlocks) {
        // ---- idx pattern, float4-vectorized (n % 4 == 0 by host guard) ----
        long long P4 = P >> 2;
        long long t = (long long)bid * TB + tid;
        if (t >= P4) return;
        long long q = t << 2;
        int nm1  = (1 << sn) - 1;
        long long nnm1 = ((long long)1 << (2 * sn)) - 1;
        int b   = (int)(q >> (2 * sn));
        int rem = (int)(q & nnm1);
        int i   = rem >> sn;
        int j   = rem & nm1;
        float rv = (float)((b << sn) + i);
        float cv = (float)((b << sn) + j);
        ((float4*)out)[t]       = make_float4(rv, rv, rv, rv);
        ((float4*)(out + P))[t] = make_float4(cv, cv + 1.f, cv + 2.f, cv + 3.f);
        return;
    }

    // ---- scatter: one thread per (edge, float4 chunk), R4-proven ----
    int t = (bid - idxBlocks) * TB + tid;
    int tot = E << s4;
    if (t >= tot) return;
    int e = t >> s4;
    int c = t & ((1 << s4) - 1);

    int u  = __ldg(&ei[e]);
    int rv = __ldg(&ei[E + e]) & ((1 << sn) - 1);

    float  p = __ldg(&pestat[(long long)e * K]);
    float4 a = __ldg(&ea4[((long long)e << s4) + c]);
    float4 w = __ldg(&w4[c]);
    float4 rr = make_float4(a.x + p * w.x, a.y + p * w.y,
                            a.z + p * w.z, a.w + p * w.w);

    long long slot = ((long long)u << sn) | rv;
    red_add_v4(val + (slot << (s4 + 2)) + (c << 2), rr);
}

// ===========================================================================
// Tier 2: R4 pow2 two-kernel path (single-store init + scatter).
// ===========================================================================
__global__ void k_init_p2(float* __restrict__ out, const float4* __restrict__ pad4,
                          int sn, long long P, int D4, int idxBlocks)
{
    if ((int)blockIdx.x < idxBlocks) {
        long long P4 = P >> 2;
        long long t = (long long)blockIdx.x * blockDim.x + threadIdx.x;
        if (t >= P4) return;
        long long q = t << 2;
        int nm1  = (1 << sn) - 1;
        long long nnm1 = ((long long)1 << (2 * sn)) - 1;
        int b   = (int)(q >> (2 * sn));
        int rem = (int)(q & nnm1);
        int i   = rem >> sn;
        int j   = rem & nm1;
        float rv = (float)((b << sn) + i);
        float cv = (float)((b << sn) + j);
        ((float4*)out)[t]       = make_float4(rv, rv, rv, rv);
        ((float4*)(out + P))[t] = make_float4(cv, cv + 1.f, cv + 2.f, cv + 3.f);
    } else {
        long long v = (long long)((int)blockIdx.x - idxBlocks) * blockDim.x
                      + threadIdx.x;
        long long V4 = P * (long long)D4;
        if (v >= V4) return;
        int c = (int)threadIdx.x & (D4 - 1);
        ((float4*)(out + 2 * P))[v] = __ldg(&pad4[c]);
    }
}

__global__ void k_scatter_p2(const int* __restrict__ ei, const float* __restrict__ pestat,
                             const float4* __restrict__ ea4, const float4* __restrict__ w4,
                             float* __restrict__ val, int E, int K, int s4, int sn)
{
    int tot = E << s4;
    int t = blockIdx.x * blockDim.x + threadIdx.x;
    if (t >= tot) return;
    int e = t >> s4;
    int c = t & ((1 << s4) - 1);
    int u = __ldg(&ei[e]);
    int rv = __ldg(&ei[E + e]) & ((1 << sn) - 1);
    float  p = __ldg(&pestat[(long long)e * K]);
    float4 a = __ldg(&ea4[((long long)e << s4) + c]);
    float4 w = __ldg(&w4[c]);
    float4 rr = make_float4(a.x + p * w.x, a.y + p * w.y,
                            a.z + p * w.z, a.w + p * w.w);
    long long slot = ((long long)u << sn) | rv;
    red_add_v4(val + (slot << (s4 + 2)) + (c << 2), rr);
}

// ===========================================================================
// Tier 3: fully generic fallbacks.
// ===========================================================================
__global__ void k_init_fused_s(float* __restrict__ out, const float* __restrict__ pad,
                               long long P, int n, int D)
{
    long long totalI = P;
    long long tot = P + P * (long long)D;
    float* val = out + 2 * P;
    long long stride = (long long)gridDim.x * blockDim.x;
    for (long long t = (long long)blockIdx.x * blockDim.x + threadIdx.x;
         t < tot; t += stride) {
        if (t < totalI) {
            long long nn = (long long)n * n;
            int b   = (int)(t / nn);
            int rem = (int)(t - (long long)b * nn);
            int i   = rem / n;
            int j   = rem - i * n;
            out[t]     = (float)(b * n + i);
            out[P + t] = (float)(b * n + j);
        } else {
            long long v = t - totalI;
            val[v] = __ldg(&pad[(int)(v % D)]);
        }
    }
}

__global__ void k_scatter_s(const int* __restrict__ ei, const float* __restrict__ pestat,
                            const float* __restrict__ ea, const float* __restrict__ w,
                            float* __restrict__ val, int E, int K, int D, int n)
{
    long long tot = (long long)E * D;
    long long stride = (long long)gridDim.x * blockDim.x;
    for (long long t = (long long)blockIdx.x * blockDim.x + threadIdx.x;
         t < tot; t += stride) {
        int e = (int)(t / D);
        int d = (int)(t - (long long)e * D);
        int u = __ldg(&ei[e]);
        int v = __ldg(&ei[E + e]);
        int g  = u / n;
        int ru = u - g * n;
        int rv = v % n;
        float p = __ldg(&pestat[(long long)e * K]);
        float x = ea[(long long)e * D + d] + p * __ldg(&w[d]);
        long long base = (((long long)g * n + ru) * n + rv) * (long long)D + d;
        atomicAdd(val + base, x);
    }
}

// ===========================================================================

static inline bool is_pow2(int x) { return x > 0 && (x & (x - 1)) == 0; }
static inline int  ilog2(int x)   { int s = 0; while ((1 << s) < x) s++; return s; }
static inline int grid_for(long long work, int tb)
{
    long long g = (work + tb - 1) / tb;
    if (g > 1048576) g = 1048576;
    if (g < 1) g = 1;
    return (int)g;
}

extern "C" void kernel_launch(void* const* d_in, const int* in_sizes, int n_in,
                              void* d_out, int out_size)
{
    // metadata order: edge_index, pestat, edge_attr, batch, fc_w, padding
    const int*   ei     = (const int*)  d_in[0];
    const float* pestat = (const float*)d_in[1];
    const float* ea     = (const float*)d_in[2];
    const float* fc_w   = (const float*)d_in[4];
    const float* pad    = (const float*)d_in[5];

    const int E = in_sizes[0] / 2;
    const int K = in_sizes[1] / E;
    const int D = in_sizes[2] / E;
    const int N = in_sizes[3];                            // dense rows = B*n
    const long long P = (long long)out_size / (D + 2);    // slots = B*n*n
    const int n = (int)(P / N);

    float* out = (float*)d_out;
    float* val = out + 2 * P;
    const int D4 = D / 4;

    const bool pow2ok = (D % 4 == 0) && (n % 4 == 0) &&
                        is_pow2(n) && is_pow2(D4) && D4 <= 256 &&
                        ((long long)E * D4 < (1LL << 31));

    if (pow2ok) {
        const int sn = ilog2(n);
        const int s4 = ilog2(D4);
        const long long V4 = P * (long long)D4;

        // K1: padding init, IPT float4 stores per thread.
        long long initBlocks = (V4 + (long long)TB * IPT - 1) / ((long long)TB * IPT);
        k_init4<<<(int)initBlocks, TB>>>((float4*)val, (const float4*)pad,
                                         V4, D4);

        // K2: idx pattern (leading) + scatter.
        const int idxBlocks  = (int)(((P >> 2) + TB - 1) / TB);
        const int scatBlocks = (int)(((long long)(E << s4) + TB - 1) / TB);
        k_idx_scatter<<<idxBlocks + scatBlocks, TB>>>(out, P, ei, pestat,
                                                      (const float4*)ea,
                                                      (const float4*)fc_w,
                                                      val, E, K, s4, sn,
                                                      idxBlocks);
    } else {
        long long tot = P + P * (long long)D;
        k_init_fused_s<<<grid_for(tot, TB), TB>>>(out, pad, P, n, D);
        long long st = (long long)E * D;
        k_scatter_s<<<grid_for(st, TB), TB>>>(ei, pestat, ea, fc_w, val,
                                              E, K, D, n);
    }
}